// round 9
// baseline (speedup 1.0000x reference)
#include <cuda_runtime.h>
#include <cuda_bf16.h>
#include <math_constants.h>

#define NB 8192
#define GRID 1024           // 1024 CTAs x 4 warps x 2 samples = 8192 samples
#define THREADS 128
#define FP_SCALE 32768.0    // 2^15 fixed point (deterministic integer accumulation)

__device__ unsigned long long g_acc;
__device__ unsigned int g_done;

// Packed fp32x2 ops (Blackwell FFMA2 path — PTX-only)
#define ADDX2(d, a, b)    asm("add.rn.f32x2 %0,%1,%2;"    : "=l"(d) : "l"(a), "l"(b))
#define FMAX2(d, a, b, c) asm("fma.rn.f32x2 %0,%1,%2,%3;" : "=l"(d) : "l"(a), "l"(b), "l"(c))
#define PACKX2(d, lo, hi) asm("mov.b64 %0,{%1,%2};"       : "=l"(d) : "f"(lo), "f"(hi))
#define UNPACKX2(lo, hi, d) asm("mov.b64 {%0,%1},%2;"     : "=f"(lo), "=f"(hi) : "l"(d))

// 128-bit load with 256B L2 prefetch granularity (R8 win: +0.35 TB/s HBM)
__device__ __forceinline__ float4 ld4_pf(const float4* p) {
    float4 v;
    asm volatile("ld.global.nc.L2::256B.v4.f32 {%0,%1,%2,%3}, [%4];"
                 : "=f"(v.x), "=f"(v.y), "=f"(v.z), "=f"(v.w) : "l"(p));
    return v;
}

// Bulk DRAM->L2 staging via the async-bulk engine: deep request stream,
// no SMEM/mbarrier/registers. Fire-and-forget.
__device__ __forceinline__ void bulk_prefetch_l2(const void* p, unsigned bytes) {
    asm volatile("cp.async.bulk.prefetch.L2.global [%0], %1;"
                 :: "l"(p), "r"(bytes) : "memory");
}

__global__ void __launch_bounds__(THREADS, 7)
loss_kernel(const float* __restrict__ x, float* __restrict__ out) {
    const int t = threadIdx.x;
    const int w = t >> 5;
    const int l = t & 31;
    const int warp_g = blockIdx.x * 4 + w;

    __shared__ float wloss[4];

    // Stage this warp's SECOND sample (16 KiB) into L2 while we process the
    // first via demand loads. Overlaps the two halves' DRAM transfers.
    if (l == 0)
        bulk_prefetch_l2(x + (size_t)(warp_g + 4096) * 4096, 16384u);

    const unsigned long long C23 = 0x4040000040000000ULL; // (2.0f, 3.0f)
    const unsigned long long C49 = 0x4110000040800000ULL; // (4.0f, 9.0f)

    float acc_loss = 0.f;

    #pragma unroll
    for (int s = 0; s < 2; ++s) {
        const int b = warp_g + s * 4096;
        const float4* __restrict__ xp =
            reinterpret_cast<const float4*>(x) + (size_t)b * 1024 + l;

        // Packed accumulators (bit-zero == (0.f, 0.f))
        unsigned long long s0p = 0, Up = 0, Vp = 0, mp1 = 0, mp2 = 0;
        float sy = 0.f;
        float bv = -CUDART_INF_F;
        int   bi = 0x7fffffff;

        // 4-deep rolling prefetch over 32 chunks (8 groups of 4)
        float4 buf[4];
        #pragma unroll
        for (int i = 0; i < 4; ++i) buf[i] = ld4_pf(&xp[i * 32]);

        #pragma unroll
        for (int g = 0; g < 8; ++g) {
            float4 nbuf[4];
            if (g < 7) {
                #pragma unroll
                for (int i = 0; i < 4; ++i)
                    nbuf[i] = ld4_pf(&xp[(g + 1) * 128 + i * 32]);
            }
            #pragma unroll
            for (int i = 0; i < 4; ++i) {
                const int c = g * 4 + i;            // chunk index 0..31
                const float X = buf[i].x, Y = buf[i].y, Z = buf[i].z, W = buf[i].w;
                unsigned long long p0, p1, lsp;
                PACKX2(p0, X, Y);
                PACKX2(p1, Z, W);
                ADDX2(lsp, p0, p1);                 // (X+Z, Y+W)
                ADDX2(s0p, s0p, lsp);               // running sum
                ADDX2(Up,  Up,  s0p);               // prefix of prefix -> c-moment
                ADDX2(Vp,  Vp,  Up);                // -> c^2-moment
                FMAX2(mp1, p1, C23, mp1);           // 2Z + 3W
                FMAX2(mp2, p1, C49, mp2);           // 4Z + 9W
                sy += Y;                            // Y coeff is 1 in both m1,m2

                const float m = fmaxf(fmaxf(X, Y), fmaxf(Z, W));
                if (m > bv) {                       // first-max: strict '>', c ascending
                    bv = m;
                    const int cc = (m == X) ? 0 : ((m == Y) ? 1 : ((m == Z) ? 2 : 3));
                    bi = ((c * 32 + l) << 2) + cc;
                }
            }
            #pragma unroll
            for (int i = 0; i < 4; ++i) buf[i] = nbuf[i];
        }

        // ---- fold packed accumulators ----
        float s0lo, s0hi, Ulo, Uhi, Vlo, Vhi, m1lo, m1hi, m2lo, m2hi;
        UNPACKX2(s0lo, s0hi, s0p);
        UNPACKX2(Ulo, Uhi, Up);
        UNPACKX2(Vlo, Vhi, Vp);
        UNPACKX2(m1lo, m1hi, mp1);
        UNPACKX2(m2lo, m2hi, mp2);

        float s0 = s0lo + s0hi;
        const float cU = Ulo + Uhi;
        const float cV = Vlo + Vhi;
        // Sum c*ls = 32*s0 - U ;  Sum c^2*ls = 1024*s0 - 65*U + 2*V
        const float sc1 = fmaf(32.f, s0, -cU);
        const float sc2 = fmaf(1024.f, s0, fmaf(-65.f, cU, 2.f * cV));
        // j = 2c + jh
        const float jh = (float)(l >> 4);
        float sj  = fmaf(2.f, sc1, jh * s0);
        float sjj = fmaf(4.f, sc2, fmaf(4.f * jh, sc1, jh * s0)); // jh^2 == jh
        // k = k0 + cc  (k0 thread-constant)
        const float m1 = sy + m1lo + m1hi;
        const float m2 = sy + m2lo + m2hi;
        const float k0 = (float)((l & 15) << 2);
        float sk  = fmaf(k0, s0, m1);
        const float skk = fmaf(k0 * k0, s0, fmaf(2.f * k0, m1, m2));
        float sq = sjj + skk;

        // ---- warp-only reduction ----
        #pragma unroll
        for (int off = 16; off > 0; off >>= 1) {
            s0 += __shfl_down_sync(0xffffffffu, s0, off);
            sj += __shfl_down_sync(0xffffffffu, sj, off);
            sk += __shfl_down_sync(0xffffffffu, sk, off);
            sq += __shfl_down_sync(0xffffffffu, sq, off);
            const float ov = __shfl_down_sync(0xffffffffu, bv, off);
            const int   oi = __shfl_down_sync(0xffffffffu, bi, off);
            if (ov > bv || (ov == bv && oi < bi)) { bv = ov; bi = oi; }
        }

        if (l == 0) {
            const float mx = (float)(bi >> 6);
            const float my = (float)(bi & 63);
            acc_loss += (mx * mx + my * my) * s0
                      - 2.f * mx * sj
                      - 2.f * my * sk
                      + sq;
        }
    }

    if (l == 0) wloss[w] = acc_loss;
    __syncthreads();

    if (t == 0) {
        const double tot = (double)wloss[0] + (double)wloss[1]
                         + (double)wloss[2] + (double)wloss[3];
        const long long q = llrint(tot * FP_SCALE);
        atomicAdd(&g_acc, (unsigned long long)q);
        __threadfence();
        const unsigned int n = atomicAdd(&g_done, 1u);
        if (n == GRID - 1u) {
            const long long totq = (long long)atomicExch(&g_acc, 0ULL);
            g_done = 0;
            out[0] = (float)((double)totq / FP_SCALE);
        }
    }
}

extern "C" void kernel_launch(void* const* d_in, const int* in_sizes, int n_in,
                              void* d_out, int out_size) {
    const float* x = (const float*)d_in[0];
    float* out = (float*)d_out;
    loss_kernel<<<GRID, THREADS>>>(x, out);
}

// round 10
// speedup vs baseline: 1.0578x; 1.0578x over previous
#include <cuda_runtime.h>
#include <cuda_bf16.h>
#include <math_constants.h>
#include <cstdint>

#define NB 8192
#define GRID 2048           // 2048 CTAs x 4 warps x 1 sample = 8192 samples
#define THREADS 128
#define FP_SCALE 32768.0

__device__ unsigned long long g_acc;
__device__ unsigned int g_done;

// Packed fp32x2 ops (Blackwell FFMA2 path — PTX-only)
#define ADDX2(d, a, b)    asm("add.rn.f32x2 %0,%1,%2;"    : "=l"(d) : "l"(a), "l"(b))
#define FMAX2(d, a, b, c) asm("fma.rn.f32x2 %0,%1,%2,%3;" : "=l"(d) : "l"(a), "l"(b), "l"(c))
#define PACK2(d, lo, hi)  asm("mov.b64 %0,{%1,%2};"       : "=l"(d) : "r"(lo), "r"(hi))
#define UNPACKX2(lo, hi, d) asm("mov.b64 {%0,%1},%2;"     : "=f"(lo), "=f"(hi) : "l"(d))

// 256-bit demand load + 256B L2 refill granularity: widest demand path,
// max useful bytes in flight per L2 miss (the only lever that moved the
// 5.2 TB/s plateau so far).
__device__ __forceinline__ void ld8_pf(const float* p, uint32_t* r) {
    asm volatile("ld.global.nc.L2::256B.v8.b32 {%0,%1,%2,%3,%4,%5,%6,%7}, [%8];"
                 : "=r"(r[0]), "=r"(r[1]), "=r"(r[2]), "=r"(r[3]),
                   "=r"(r[4]), "=r"(r[5]), "=r"(r[6]), "=r"(r[7]) : "l"(p));
}

__global__ void __launch_bounds__(THREADS)
loss_kernel(const float* __restrict__ x, float* __restrict__ out) {
    const int t = threadIdx.x;
    const int w = t >> 5;
    const int l = t & 31;
    const int b = blockIdx.x * 4 + w;   // sample index (warp-uniform)

    __shared__ float wloss[4];

    const float* __restrict__ xp = x + (size_t)b * 4096 + (size_t)l * 8;

    // m1 coeff pairs (c):   x2,x3 | x4,x5 | x6,x7   (x1 coeff is 1 -> sy)
    const unsigned long long C23 = 0x4040000040000000ULL; // (2,3)
    const unsigned long long C45 = 0x40A0000040800000ULL; // (4,5)
    const unsigned long long C67 = 0x40E0000040C00000ULL; // (6,7)
    // m2 coeff pairs (c^2)
    const unsigned long long Q49   = 0x4110000040800000ULL; // (4,9)
    const unsigned long long Q1625 = 0x41C8000041800000ULL; // (16,25)
    const unsigned long long Q3649 = 0x4244000042100000ULL; // (36,49)

    unsigned long long s0p = 0, Up = 0, Vp = 0, mp1 = 0, mp2 = 0;
    float sy = 0.f;
    float bv = -CUDART_INF_F;
    int   bi = 0x7fffffff;

    // 4-deep rolling ring of 32B loads: 4KB in flight per warp
    uint32_t buf[4][8];
    #pragma unroll
    for (int i = 0; i < 4; ++i) ld8_pf(xp + i * 256, buf[i]);

    #pragma unroll
    for (int it = 0; it < 16; ++it) {
        const uint32_t* r = buf[it & 3];

        unsigned long long p0, p1, p2, p3;
        PACK2(p0, r[0], r[1]);
        PACK2(p1, r[2], r[3]);
        PACK2(p2, r[4], r[5]);
        PACK2(p3, r[6], r[7]);

        unsigned long long t0, t1, lsp;
        ADDX2(t0, p0, p1);
        ADDX2(t1, p2, p3);
        ADDX2(lsp, t0, t1);
        ADDX2(s0p, s0p, lsp);
        ADDX2(Up,  Up,  s0p);
        ADDX2(Vp,  Vp,  Up);
        FMAX2(mp1, p1, C23, mp1);
        FMAX2(mp1, p2, C45, mp1);
        FMAX2(mp1, p3, C67, mp1);
        FMAX2(mp2, p1, Q49,   mp2);
        FMAX2(mp2, p2, Q1625, mp2);
        FMAX2(mp2, p3, Q3649, mp2);

        const float x0 = __uint_as_float(r[0]);
        const float x1 = __uint_as_float(r[1]);
        const float x2 = __uint_as_float(r[2]);
        const float x3 = __uint_as_float(r[3]);
        const float x4 = __uint_as_float(r[4]);
        const float x5 = __uint_as_float(r[5]);
        const float x6 = __uint_as_float(r[6]);
        const float x7 = __uint_as_float(r[7]);
        sy += x1;

        const float m = fmaxf(fmaxf(fmaxf(x0, x1), fmaxf(x2, x3)),
                              fmaxf(fmaxf(x4, x5), fmaxf(x6, x7)));
        if (m > bv) {           // first-max: within-thread indices ascend
            bv = m;
            int cc;
            if      (m == x0) cc = 0;
            else if (m == x1) cc = 1;
            else if (m == x2) cc = 2;
            else if (m == x3) cc = 3;
            else if (m == x4) cc = 4;
            else if (m == x5) cc = 5;
            else if (m == x6) cc = 6;
            else              cc = 7;
            bi = ((it * 32 + l) << 3) + cc;
        }

        // refill drained slot with load 4 ahead
        if (it < 12) ld8_pf(xp + (it + 4) * 256, buf[it & 3]);
    }

    // ---- fold packed accumulators (T = 16 iterations) ----
    float s0lo, s0hi, Ulo, Uhi, Vlo, Vhi, m1lo, m1hi, m2lo, m2hi;
    UNPACKX2(s0lo, s0hi, s0p);
    UNPACKX2(Ulo, Uhi, Up);
    UNPACKX2(Vlo, Vhi, Vp);
    UNPACKX2(m1lo, m1hi, mp1);
    UNPACKX2(m2lo, m2hi, mp2);

    float s0 = s0lo + s0hi;
    const float cU = Ulo + Uhi;
    const float cV = Vlo + Vhi;
    const float si1 = fmaf(16.f, s0, -cU);                         // sum it*ls
    const float si2 = fmaf(256.f, s0, fmaf(-33.f, cU, 2.f * cV));  // sum it^2*ls
    // j = 4*it + jb,  jb = l>>3
    const float jb = (float)(l >> 3);
    float sj  = fmaf(4.f, si1, jb * s0);
    float sjj = fmaf(16.f, si2, fmaf(8.f * jb, si1, jb * jb * s0));
    // k = k0 + c,  k0 = (l&7)*8
    const float m1 = sy + m1lo + m1hi;
    const float m2 = sy + m2lo + m2hi;
    const float k0 = (float)((l & 7) << 3);
    float sk  = fmaf(k0, s0, m1);
    const float skk = fmaf(k0 * k0, s0, fmaf(2.f * k0, m1, m2));
    float sq = sjj + skk;

    // ---- warp-only reduction ----
    #pragma unroll
    for (int off = 16; off > 0; off >>= 1) {
        s0 += __shfl_down_sync(0xffffffffu, s0, off);
        sj += __shfl_down_sync(0xffffffffu, sj, off);
        sk += __shfl_down_sync(0xffffffffu, sk, off);
        sq += __shfl_down_sync(0xffffffffu, sq, off);
        const float ov = __shfl_down_sync(0xffffffffu, bv, off);
        const int   oi = __shfl_down_sync(0xffffffffu, bi, off);
        if (ov > bv || (ov == bv && oi < bi)) { bv = ov; bi = oi; }
    }

    if (l == 0) {
        const float mx = (float)(bi >> 6);
        const float my = (float)(bi & 63);
        wloss[w] = (mx * mx + my * my) * s0 - 2.f * mx * sj - 2.f * my * sk + sq;
    }
    __syncthreads();

    if (t == 0) {
        const double tot = (double)wloss[0] + (double)wloss[1]
                         + (double)wloss[2] + (double)wloss[3];
        const long long q = llrint(tot * FP_SCALE);
        atomicAdd(&g_acc, (unsigned long long)q);
        __threadfence();
        const unsigned int n = atomicAdd(&g_done, 1u);
        if (n == GRID - 1u) {
            const long long totq = (long long)atomicExch(&g_acc, 0ULL);
            g_done = 0;
            out[0] = (float)((double)totq / FP_SCALE);
        }
    }
}

extern "C" void kernel_launch(void* const* d_in, const int* in_sizes, int n_in,
                              void* d_out, int out_size) {
    const float* x = (const float*)d_in[0];
    float* out = (float*)d_out;
    loss_kernel<<<GRID, THREADS>>>(x, out);
}